// round 1
// baseline (speedup 1.0000x reference)
#include <cuda_runtime.h>
#include <math.h>

// ---------------- problem constants ----------------
#define TLEN   2048
#define LOGT   11
#define NHALF  1024          // TLEN/2
#define NSAMP  48            // B*C = 8*6
#define NCH    6
#define N1     80            // J*Q = 10*8
#define NK     10            // J
#define NPAIR  360           // sum_{k=1..9} 8k
#define NCOEF  440           // N1 + NPAIR
#define NTHREADS 256

// ---------------- device scratch (static; no allocations) ----------------
__device__ float2 g_xh[NSAMP][TLEN];          // FFT of each flattened signal
__device__ float2 g_U1h[NSAMP][N1][TLEN];     // fft(|ifft(xh*psi1)|), cached for stage 2
__device__ float  g_psi1[N1][TLEN];
__device__ float  g_psi2[NK][TLEN];
__device__ float  g_phi[TLEN];
__device__ float2 g_tw[NHALF];                // exp(-2*pi*i*k/T), k in [0,1024)

// ---------------- filter / twiddle init ----------------
__global__ void init_filters() {
    int i = blockIdx.x * blockDim.x + threadIdx.x;
    if (i < NHALF) {
        double s, c;
        sincospi(-2.0 * (double)i / (double)TLEN, &s, &c);
        g_tw[i] = make_float2((float)c, (float)s);
    }
    if (i < TLEN) {
        float f = (i < TLEN / 2) ? (float)i / (float)TLEN
                                 : (float)(i - TLEN) / (float)TLEN;
        const float sigphi = 0.8f * 0.4f * exp2f(-10.0f);   // BW_RATIO*XI_MAX*2^-J
        g_phi[i] = expf(-(f * f) / (2.0f * sigphi * sigphi));
        for (int j = 0; j < N1; j++) {
            float xi  = 0.4f * exp2f(-(float)j / 8.0f);
            float sig = 0.8f * xi / 8.0f;
            float d   = f - xi;
            g_psi1[j][i] = expf(-d * d / (2.0f * sig * sig));
        }
        for (int k = 0; k < NK; k++) {
            float xi  = 0.4f * exp2f(-(float)k);
            float sig = 0.8f * xi;
            float d   = f - xi;
            g_psi2[k][i] = expf(-d * d / (2.0f * sig * sig));
        }
    }
}

// ---------------- in-place radix-2 DIT block FFT (unnormalized) ----------------
// inverse=0: X[k] = sum x[t] e^{-2pi i kt/T};  inverse=1: conj twiddles.
__device__ __forceinline__ void block_fft(float* re, float* im,
                                          const float* twr, const float* twi,
                                          int inverse) {
    const int tid = threadIdx.x;
    // bit-reversal permutation (disjoint pair swaps)
    #pragma unroll
    for (int i = tid; i < TLEN; i += NTHREADS) {
        int r = (int)(__brev((unsigned)i) >> (32 - LOGT));
        if (i < r) {
            float a = re[i]; re[i] = re[r]; re[r] = a;
            float b = im[i]; im[i] = im[r]; im[r] = b;
        }
    }
    __syncthreads();
    float wsign = inverse ? -1.0f : 1.0f;
    for (int half = 1; half < TLEN; half <<= 1) {
        int step = NHALF / half;          // twiddle stride = T/len
        for (int b = tid; b < NHALF; b += NTHREADS) {
            int j  = b & (half - 1);
            int i0 = ((b - j) << 1) + j;  // group*len + j
            int i1 = i0 + half;
            int ti = j * step;
            float wr = twr[ti];
            float wi = twi[ti] * wsign;
            float vr = re[i1], vi = im[i1];
            float tr = vr * wr - vi * wi;
            float tq = vr * wi + vi * wr;
            float ur = re[i0], ui = im[i0];
            re[i0] = ur + tr; im[i0] = ui + tq;
            re[i1] = ur - tr; im[i1] = ui - tq;
        }
        __syncthreads();
    }
}

#define LOAD_TW()                                                   \
    for (int i = threadIdx.x; i < NHALF; i += NTHREADS) {           \
        float2 w = g_tw[i]; s_twr[i] = w.x; s_twi[i] = w.y;         \
    }

// ---------------- forward FFT of input signals ----------------
__global__ void fft_x_kernel(const float* __restrict__ x) {
    __shared__ float s_re[TLEN], s_im[TLEN];
    __shared__ float s_twr[NHALF], s_twi[NHALF];
    int n = blockIdx.x;               // flattened signal: n = b*6 + ch
    int b = n / NCH, ch = n % NCH;
    LOAD_TW();
    for (int t = threadIdx.x; t < TLEN; t += NTHREADS) {
        s_re[t] = x[(b * TLEN + t) * NCH + ch];   // x[b, t, ch]
        s_im[t] = 0.0f;
    }
    __syncthreads();
    block_fft(s_re, s_im, s_twr, s_twi, 0);
    for (int i = threadIdx.x; i < TLEN; i += NTHREADS)
        g_xh[n][i] = make_float2(s_re[i], s_im[i]);
}

// ---------------- shared epilogue: mean of log(re*invT + eps) ----------------
__device__ __forceinline__ void reduce_meanlog(const float* re, float* red,
                                               float* out_elem) {
    const float invT = 1.0f / (float)TLEN;
    int tid = threadIdx.x;
    float s = 0.0f;
    for (int i = tid; i < TLEN; i += NTHREADS)
        s += logf(re[i] * invT + 1e-6f);
    red[tid] = s;
    __syncthreads();
    for (int o = NTHREADS / 2; o > 0; o >>= 1) {
        if (tid < o) red[tid] += red[tid + o];
        __syncthreads();
    }
    if (tid == 0) *out_elem = red[0] * invT;
}

// ---------------- stage 1: one CTA per (signal n, first-order filter j) ----------------
__global__ void stage1_kernel(float* __restrict__ out) {
    __shared__ float s_re[TLEN], s_im[TLEN];
    __shared__ float s_twr[NHALF], s_twi[NHALF];
    __shared__ float s_red[NTHREADS];
    const int n = blockIdx.x;     // 0..47
    const int j = blockIdx.y;     // 0..79
    const int tid = threadIdx.x;
    const float invT = 1.0f / (float)TLEN;
    LOAD_TW();
    const float* psi = g_psi1[j];
    for (int i = tid; i < TLEN; i += NTHREADS) {
        float p = psi[i];
        float2 xh = g_xh[n][i];
        s_re[i] = xh.x * p;
        s_im[i] = xh.y * p;
    }
    __syncthreads();
    block_fft(s_re, s_im, s_twr, s_twi, 1);           // ifft (unnormalized)
    for (int i = tid; i < TLEN; i += NTHREADS) {      // U1 = |.|/T
        float a = sqrtf(s_re[i] * s_re[i] + s_im[i] * s_im[i]) * invT;
        s_re[i] = a; s_im[i] = 0.0f;
    }
    __syncthreads();
    block_fft(s_re, s_im, s_twr, s_twi, 0);           // U1h = fft(U1)
    for (int i = tid; i < TLEN; i += NTHREADS) {
        float rr = s_re[i], ii = s_im[i];
        g_U1h[n][j][i] = make_float2(rr, ii);         // cache for stage 2
        float p = g_phi[i];
        s_re[i] = rr * p; s_im[i] = ii * p;
    }
    __syncthreads();
    block_fft(s_re, s_im, s_twr, s_twi, 1);           // S1 = ifft(U1h*phi)/T
    int b = n / NCH, ch = n % NCH;
    reduce_meanlog(s_re, s_red, &out[(b * NCOEF + j) * NCH + ch]);
}

// ---------------- stage 2: one CTA per (signal n, pair p) ----------------
__global__ void stage2_kernel(float* __restrict__ out) {
    __shared__ float s_re[TLEN], s_im[TLEN];
    __shared__ float s_twr[NHALF], s_twi[NHALF];
    __shared__ float s_red[NTHREADS];
    const int n = blockIdx.x;     // 0..47
    const int p = blockIdx.y;     // 0..359
    const int tid = threadIdx.x;
    const float invT = 1.0f / (float)TLEN;
    // decode pair: reference order is k-major, j1 = 0..8k-1 within band k
    int k = 1, pp = p;
    while (pp >= 8 * k) { pp -= 8 * k; k++; }
    int j1 = pp;
    LOAD_TW();
    const float* psi = g_psi2[k];
    const float2* u1h = g_U1h[n][j1];
    for (int i = tid; i < TLEN; i += NTHREADS) {
        float ps = psi[i];
        float2 u = u1h[i];
        s_re[i] = u.x * ps;
        s_im[i] = u.y * ps;
    }
    __syncthreads();
    block_fft(s_re, s_im, s_twr, s_twi, 1);           // ifft
    for (int i = tid; i < TLEN; i += NTHREADS) {      // U2 = |.|/T
        float a = sqrtf(s_re[i] * s_re[i] + s_im[i] * s_im[i]) * invT;
        s_re[i] = a; s_im[i] = 0.0f;
    }
    __syncthreads();
    block_fft(s_re, s_im, s_twr, s_twi, 0);           // fft(U2)
    for (int i = tid; i < TLEN; i += NTHREADS) {
        float ph = g_phi[i];
        s_re[i] *= ph; s_im[i] *= ph;
    }
    __syncthreads();
    block_fft(s_re, s_im, s_twr, s_twi, 1);           // S2 = ifft(.)/T
    int b = n / NCH, ch = n % NCH;
    reduce_meanlog(s_re, s_red, &out[(b * NCOEF + N1 + p) * NCH + ch]);
}

// ---------------- launcher ----------------
extern "C" void kernel_launch(void* const* d_in, const int* in_sizes, int n_in,
                              void* d_out, int out_size) {
    const float* x = (const float*)d_in[0];   // [8, 2048, 6] f32
    float* out = (float*)d_out;               // [8, 440, 6] f32
    init_filters<<<(TLEN + NTHREADS - 1) / NTHREADS, NTHREADS>>>();
    fft_x_kernel<<<NSAMP, NTHREADS>>>(x);
    stage1_kernel<<<dim3(NSAMP, N1), NTHREADS>>>(out);
    stage2_kernel<<<dim3(NSAMP, NPAIR), NTHREADS>>>(out);
}

// round 2
// speedup vs baseline: 7.1032x; 7.1032x over previous
#include <cuda_runtime.h>
#include <math.h>

// ---------------- problem constants ----------------
#define TLEN   2048
#define NSAMP  48            // B*C = 8*6
#define NCH    6
#define N1     80            // J*Q = 10*8
#define NK     10            // J
#define NPAIR  360
#define NCOEF  440
#define NT     256
#define SQ2H   0.70710678118654752f

// ---------------- device scratch (static; no allocations) ----------------
// All frequency-domain arrays stored in SWIZZLED-DIGIT-REVERSED physical order.
__device__ float g_xh_re[NSAMP][TLEN], g_xh_im[NSAMP][TLEN];
__device__ float g_u1h_re[NSAMP][N1][TLEN], g_u1h_im[NSAMP][N1][TLEN];
__device__ float g_psi1[N1][TLEN];
__device__ float g_psi2[NK][TLEN];
__device__ float g_phi[TLEN];

// XOR swizzle: injects bits[7:5] into bits[4:2]. Involution. Makes all FFT
// pass strides (256, 32, 4, 1) bank-conflict-free.
__device__ __forceinline__ int SW(int i) { return i ^ ((i >> 3) & 28); }

// ---------------- register radix kernels ----------------
// Full 8-point DFT: y_k = sum_u x_u * exp(sgn*2*pi*i*k*u/8). sgn=-1 fwd, +1 inv.
__device__ __forceinline__ void dft8(float xr[8], float xi[8], const float sgn) {
    float t0r = xr[0] + xr[4], t0i = xi[0] + xi[4];
    float t1r = xr[0] - xr[4], t1i = xi[0] - xi[4];
    float t2r = xr[2] + xr[6], t2i = xi[2] + xi[6];
    float t3r = xr[2] - xr[6], t3i = xi[2] - xi[6];
    float it3r = -sgn * t3i, it3i = sgn * t3r;
    float E0r = t0r + t2r, E0i = t0i + t2i;
    float E2r = t0r - t2r, E2i = t0i - t2i;
    float E1r = t1r + it3r, E1i = t1i + it3i;
    float E3r = t1r - it3r, E3i = t1i - it3i;
    float u0r = xr[1] + xr[5], u0i = xi[1] + xi[5];
    float u1r = xr[1] - xr[5], u1i = xi[1] - xi[5];
    float u2r = xr[3] + xr[7], u2i = xi[3] + xi[7];
    float u3r = xr[3] - xr[7], u3i = xi[3] - xi[7];
    float iu3r = -sgn * u3i, iu3i = sgn * u3r;
    float O0r = u0r + u2r, O0i = u0i + u2i;
    float O2r = u0r - u2r, O2i = u0i - u2i;
    float O1r = u1r + iu3r, O1i = u1i + iu3i;
    float O3r = u1r - iu3r, O3i = u1i - iu3i;
    float w1i = sgn * SQ2H;
    float a1r = O1r * SQ2H - O1i * w1i, a1i = O1r * w1i + O1i * SQ2H;
    float a2r = -sgn * O2i,             a2i = sgn * O2r;
    float a3r = -O3r * SQ2H - O3i * w1i, a3i = O3r * w1i - O3i * SQ2H;
    xr[0] = E0r + O0r; xi[0] = E0i + O0i;
    xr[4] = E0r - O0r; xi[4] = E0i - O0i;
    xr[1] = E1r + a1r; xi[1] = E1i + a1i;
    xr[5] = E1r - a1r; xi[5] = E1i - a1i;
    xr[2] = E2r + a2r; xi[2] = E2i + a2i;
    xr[6] = E2r - a2r; xi[6] = E2i - a2i;
    xr[3] = E3r + a3r; xi[3] = E3i + a3i;
    xr[7] = E3r - a3r; xi[7] = E3i - a3i;
}

// One radix-8 pass on sub-blocks of size L (in-place, swizzled smem).
// DIF (dit=false): DFT8 then twiddle outputs.  DIT (dit=true): twiddle inputs
// then DFT8. Twiddle w^t with w = exp(sgn*2*pi*i*j/L).
__device__ __forceinline__ void pass8(float* re, float* im, const int L,
                                      const float sgn, const bool dit) {
    const int S = L >> 3;
    const int tid = threadIdx.x;
    const int j = tid & (S - 1);
    const int base = ((tid & ~(S - 1)) << 3) + j;   // c*L + j
    float xr[8], xi[8];
#pragma unroll
    for (int t = 0; t < 8; t++) {
        int p = SW(base + t * S);
        xr[t] = re[p]; xi[t] = im[p];
    }
    float ang = sgn * 6.2831853071795864f * (float)j / (float)L;
    float ws, wc;
    __sincosf(ang, &ws, &wc);
    if (dit) {
        float cr = wc, ci = ws;
#pragma unroll
        for (int t = 1; t < 8; t++) {
            float r = xr[t] * cr - xi[t] * ci;
            xi[t] = xr[t] * ci + xi[t] * cr; xr[t] = r;
            float nr = cr * wc - ci * ws; ci = cr * ws + ci * wc; cr = nr;
        }
        dft8(xr, xi, sgn);
    } else {
        dft8(xr, xi, sgn);
        float cr = wc, ci = ws;
#pragma unroll
        for (int t = 1; t < 8; t++) {
            float r = xr[t] * cr - xi[t] * ci;
            xi[t] = xr[t] * ci + xi[t] * cr; xr[t] = r;
            float nr = cr * wc - ci * ws; ci = cr * ws + ci * wc; cr = nr;
        }
    }
#pragma unroll
    for (int t = 0; t < 8; t++) {
        int p = SW(base + t * S);
        re[p] = xr[t]; im[p] = xi[t];
    }
}

// Final radix-4 pass, L=4 (twiddle = 1). Vectorized float4; SW preserves
// aligned 4-groups (only bits 2-4 are XORed).
__device__ __forceinline__ void pass4(float* re, float* im, const float sgn) {
    const int tid = threadIdx.x;
#pragma unroll
    for (int h = 0; h < 2; h++) {
        int c = tid + h * NT;
        int p = SW(c << 2);
        float4 r = *(float4*)(re + p);
        float4 q = *(float4*)(im + p);
        float t0r = r.x + r.z, t0i = q.x + q.z;
        float t1r = r.x - r.z, t1i = q.x - q.z;
        float t2r = r.y + r.w, t2i = q.y + q.w;
        float t3r = r.y - r.w, t3i = q.y - q.w;
        float it3r = -sgn * t3i, it3i = sgn * t3r;
        r.x = t0r + t2r; q.x = t0i + t2i;
        r.z = t0r - t2r; q.z = t0i - t2i;
        r.y = t1r + it3r; q.y = t1i + it3i;
        r.w = t1r - it3r; q.w = t1i - it3i;
        *(float4*)(re + p) = r;
        *(float4*)(im + p) = q;
    }
}

// Caller must __syncthreads() before. Both end with a sync.
__device__ __forceinline__ void fft_fwd(float* re, float* im) {
    pass8(re, im, 2048, -1.f, false); __syncthreads();
    pass8(re, im, 256,  -1.f, false); __syncthreads();
    pass8(re, im, 32,   -1.f, false); __syncthreads();
    pass4(re, im, -1.f);              __syncthreads();
}
__device__ __forceinline__ void fft_inv(float* re, float* im) {
    pass4(re, im, 1.f);               __syncthreads();
    pass8(re, im, 32,   1.f, true);   __syncthreads();
    pass8(re, im, 256,  1.f, true);   __syncthreads();
    pass8(re, im, 2048, 1.f, true);   __syncthreads();
}

// ---------------- filter init (physical slot -> frequency index) ----------------
__global__ void init_filters() {
    int p = blockIdx.x * blockDim.x + threadIdx.x;
    if (p >= TLEN) return;
    int i = SW(p);                       // logical DIF position
    int a = i >> 8, b = (i >> 5) & 7, c = (i >> 2) & 7, d = i & 3;
    int k = a + 8 * b + 64 * c + 512 * d;   // true frequency bin
    float f = (float)(k < 1024 ? k : k - 2048) / 2048.0f;
    const float sigphi = 0.8f * 0.4f * exp2f(-10.0f);
    g_phi[p] = expf(-(f * f) / (2.0f * sigphi * sigphi));
    for (int j = 0; j < N1; j++) {
        float xi  = 0.4f * exp2f(-(float)j / 8.0f);
        float sig = 0.8f * xi / 8.0f;
        float dd  = f - xi;
        g_psi1[j][p] = expf(-dd * dd / (2.0f * sig * sig));
    }
    for (int kk = 0; kk < NK; kk++) {
        float xi  = 0.4f * exp2f(-(float)kk);
        float sig = 0.8f * xi;
        float dd  = f - xi;
        g_psi2[kk][p] = expf(-dd * dd / (2.0f * sig * sig));
    }
}

// ---------------- mean of log(re/T + eps) ----------------
__device__ __forceinline__ void meanlog(const float* re, float* out_elem) {
    const float invT = 1.0f / (float)TLEN;
    float s = 0.0f;
    for (int p = threadIdx.x; p < TLEN; p += NT)
        s += __logf(re[p] * invT + 1e-6f);
    for (int o = 16; o; o >>= 1) s += __shfl_xor_sync(0xFFFFFFFFu, s, o);
    __shared__ float red[NT / 32];
    if ((threadIdx.x & 31) == 0) red[threadIdx.x >> 5] = s;
    __syncthreads();
    if (threadIdx.x == 0) {
        float tot = 0.0f;
        for (int w = 0; w < NT / 32; w++) tot += red[w];
        *out_elem = tot * invT;
    }
}

// ---------------- forward FFT of input signals ----------------
__global__ void __launch_bounds__(NT) fft_x_kernel(const float* __restrict__ x) {
    __shared__ __align__(16) float sre[TLEN], sim[TLEN];
    int n = blockIdx.x, b = n / NCH, ch = n % NCH;
    for (int t = threadIdx.x; t < TLEN; t += NT) {
        sre[SW(t)] = x[(b * TLEN + t) * NCH + ch];
        sim[t] = 0.0f;
    }
    __syncthreads();
    fft_fwd(sre, sim);
    for (int p = threadIdx.x; p < TLEN; p += NT) {
        g_xh_re[n][p] = sre[p];
        g_xh_im[n][p] = sim[p];
    }
}

// ---------------- stage 1 ----------------
__global__ void __launch_bounds__(NT) stage1_kernel(float* __restrict__ out) {
    __shared__ __align__(16) float sre[TLEN], sim[TLEN];
    const int n = blockIdx.x, j = blockIdx.y;
    const int tid = threadIdx.x;
    const float invT = 1.0f / (float)TLEN;
    float4* sre4 = (float4*)sre; float4* sim4 = (float4*)sim;
    const float4* xr4 = (const float4*)g_xh_re[n];
    const float4* xi4 = (const float4*)g_xh_im[n];
    const float4* ps4 = (const float4*)g_psi1[j];
#pragma unroll
    for (int p = tid; p < TLEN / 4; p += NT) {
        float4 pr = ps4[p], ar = xr4[p], ai = xi4[p];
        float4 u, v;
        u.x = ar.x * pr.x; u.y = ar.y * pr.y; u.z = ar.z * pr.z; u.w = ar.w * pr.w;
        v.x = ai.x * pr.x; v.y = ai.y * pr.y; v.z = ai.z * pr.z; v.w = ai.w * pr.w;
        sre4[p] = u; sim4[p] = v;
    }
    __syncthreads();
    fft_inv(sre, sim);
#pragma unroll
    for (int p = tid; p < TLEN / 4; p += NT) {
        float4 a = sre4[p], bq = sim4[p], m, z;
        m.x = sqrtf(a.x * a.x + bq.x * bq.x) * invT;
        m.y = sqrtf(a.y * a.y + bq.y * bq.y) * invT;
        m.z = sqrtf(a.z * a.z + bq.z * bq.z) * invT;
        m.w = sqrtf(a.w * a.w + bq.w * bq.w) * invT;
        z.x = z.y = z.z = z.w = 0.0f;
        sre4[p] = m; sim4[p] = z;
    }
    __syncthreads();
    fft_fwd(sre, sim);
    {
        float4* ur4 = (float4*)g_u1h_re[n][j];
        float4* ui4 = (float4*)g_u1h_im[n][j];
        const float4* ph4 = (const float4*)g_phi;
#pragma unroll
        for (int p = tid; p < TLEN / 4; p += NT) {
            float4 a = sre4[p], bq = sim4[p], ph = ph4[p];
            ur4[p] = a; ui4[p] = bq;
            a.x *= ph.x; a.y *= ph.y; a.z *= ph.z; a.w *= ph.w;
            bq.x *= ph.x; bq.y *= ph.y; bq.z *= ph.z; bq.w *= ph.w;
            sre4[p] = a; sim4[p] = bq;
        }
    }
    __syncthreads();
    fft_inv(sre, sim);
    meanlog(sre, &out[((n / NCH) * NCOEF + j) * NCH + (n % NCH)]);
}

// ---------------- stage 2 ----------------
__global__ void __launch_bounds__(NT) stage2_kernel(float* __restrict__ out) {
    __shared__ __align__(16) float sre[TLEN], sim[TLEN];
    const int n = blockIdx.x, pid = blockIdx.y;
    const int tid = threadIdx.x;
    const float invT = 1.0f / (float)TLEN;
    int k = 1, pp = pid;
    while (pp >= 8 * k) { pp -= 8 * k; k++; }
    const int j1 = pp;
    float4* sre4 = (float4*)sre; float4* sim4 = (float4*)sim;
    const float4* ur4 = (const float4*)g_u1h_re[n][j1];
    const float4* ui4 = (const float4*)g_u1h_im[n][j1];
    const float4* ps4 = (const float4*)g_psi2[k];
#pragma unroll
    for (int p = tid; p < TLEN / 4; p += NT) {
        float4 pr = ps4[p], ar = ur4[p], ai = ui4[p];
        float4 u, v;
        u.x = ar.x * pr.x; u.y = ar.y * pr.y; u.z = ar.z * pr.z; u.w = ar.w * pr.w;
        v.x = ai.x * pr.x; v.y = ai.y * pr.y; v.z = ai.z * pr.z; v.w = ai.w * pr.w;
        sre4[p] = u; sim4[p] = v;
    }
    __syncthreads();
    fft_inv(sre, sim);
#pragma unroll
    for (int p = tid; p < TLEN / 4; p += NT) {
        float4 a = sre4[p], bq = sim4[p], m, z;
        m.x = sqrtf(a.x * a.x + bq.x * bq.x) * invT;
        m.y = sqrtf(a.y * a.y + bq.y * bq.y) * invT;
        m.z = sqrtf(a.z * a.z + bq.z * bq.z) * invT;
        m.w = sqrtf(a.w * a.w + bq.w * bq.w) * invT;
        z.x = z.y = z.z = z.w = 0.0f;
        sre4[p] = m; sim4[p] = z;
    }
    __syncthreads();
    fft_fwd(sre, sim);
    {
        const float4* ph4 = (const float4*)g_phi;
#pragma unroll
        for (int p = tid; p < TLEN / 4; p += NT) {
            float4 a = sre4[p], bq = sim4[p], ph = ph4[p];
            a.x *= ph.x; a.y *= ph.y; a.z *= ph.z; a.w *= ph.w;
            bq.x *= ph.x; bq.y *= ph.y; bq.z *= ph.z; bq.w *= ph.w;
            sre4[p] = a; sim4[p] = bq;
        }
    }
    __syncthreads();
    fft_inv(sre, sim);
    meanlog(sre, &out[((n / NCH) * NCOEF + N1 + pid) * NCH + (n % NCH)]);
}

// ---------------- launcher ----------------
extern "C" void kernel_launch(void* const* d_in, const int* in_sizes, int n_in,
                              void* d_out, int out_size) {
    const float* x = (const float*)d_in[0];   // [8, 2048, 6] f32
    float* out = (float*)d_out;               // [8, 440, 6] f32
    init_filters<<<(TLEN + NT - 1) / NT, NT>>>();
    fft_x_kernel<<<NSAMP, NT>>>(x);
    stage1_kernel<<<dim3(NSAMP, N1), NT>>>(out);
    stage2_kernel<<<dim3(NSAMP, NPAIR), NT>>>(out);
}

// round 3
// speedup vs baseline: 9.2925x; 1.3082x over previous
#include <cuda_runtime.h>
#include <math.h>

// ---------------- problem constants ----------------
#define TLEN   2048
#define NSAMP  48            // B*C = 8*6
#define NCH    6
#define N1     80
#define NK     10
#define NPAIR  360
#define NCOEF  440
#define NT     256
#define SQ2H   0.70710678118654752f
#define TWO_PI 6.28318530717958648f

// ---------------- device scratch (static; no allocations) ----------------
// All frequency-domain arrays stored in SWIZZLED-DIGIT-REVERSED physical order.
__device__ float g_xh_re[NSAMP][TLEN], g_xh_im[NSAMP][TLEN];
__device__ float g_u1h_re[NSAMP][N1][TLEN], g_u1h_im[NSAMP][N1][TLEN];
__device__ float g_psi1[N1][TLEN];
__device__ float g_psi2[NK][TLEN];
__device__ float g_phi[TLEN];

// XOR swizzle (involution): conflict-free for pass strides 256/32/4/1.
__device__ __forceinline__ int SW(int i) { return i ^ ((i >> 3) & 28); }

// ---------------- full 8-point DFT (sgn=-1 fwd, +1 inv) ----------------
__device__ __forceinline__ void dft8(float xr[8], float xi[8], const float sgn) {
    float t0r = xr[0] + xr[4], t0i = xi[0] + xi[4];
    float t1r = xr[0] - xr[4], t1i = xi[0] - xi[4];
    float t2r = xr[2] + xr[6], t2i = xi[2] + xi[6];
    float t3r = xr[2] - xr[6], t3i = xi[2] - xi[6];
    float it3r = -sgn * t3i, it3i = sgn * t3r;
    float E0r = t0r + t2r, E0i = t0i + t2i;
    float E2r = t0r - t2r, E2i = t0i - t2i;
    float E1r = t1r + it3r, E1i = t1i + it3i;
    float E3r = t1r - it3r, E3i = t1i - it3i;
    float u0r = xr[1] + xr[5], u0i = xi[1] + xi[5];
    float u1r = xr[1] - xr[5], u1i = xi[1] - xi[5];
    float u2r = xr[3] + xr[7], u2i = xi[3] + xi[7];
    float u3r = xr[3] - xr[7], u3i = xi[3] - xi[7];
    float iu3r = -sgn * u3i, iu3i = sgn * u3r;
    float O0r = u0r + u2r, O0i = u0i + u2i;
    float O2r = u0r - u2r, O2i = u0i - u2i;
    float O1r = u1r + iu3r, O1i = u1i + iu3i;
    float O3r = u1r - iu3r, O3i = u1i - iu3i;
    float w1i = sgn * SQ2H;
    float a1r = O1r * SQ2H - O1i * w1i, a1i = O1r * w1i + O1i * SQ2H;
    float a2r = -sgn * O2i,             a2i = sgn * O2r;
    float a3r = -O3r * SQ2H - O3i * w1i, a3i = O3r * w1i - O3i * SQ2H;
    xr[0] = E0r + O0r; xi[0] = E0i + O0i;
    xr[4] = E0r - O0r; xi[4] = E0i - O0i;
    xr[1] = E1r + a1r; xi[1] = E1i + a1i;
    xr[5] = E1r - a1r; xi[5] = E1i - a1i;
    xr[2] = E2r + a2r; xi[2] = E2i + a2i;
    xr[6] = E2r - a2r; xi[6] = E2i - a2i;
    xr[3] = E3r + a3r; xi[3] = E3i + a3i;
    xr[7] = E3r - a3r; xi[7] = E3i - a3i;
}

// twiddle x[t] *= w^t, w = (c, s), via recurrence
__device__ __forceinline__ void twiddle8(float xr[8], float xi[8],
                                         const float c, const float s) {
    float cr = c, ci = s;
#pragma unroll
    for (int t = 1; t < 8; t++) {
        float r = xr[t] * cr - xi[t] * ci;
        xi[t] = xr[t] * ci + xi[t] * cr; xr[t] = r;
        float nr = cr * c - ci * s; ci = cr * s + ci * c; cr = nr;
    }
}

__device__ __forceinline__ void load8(const float* a, int base, int S, float v[8]) {
#pragma unroll
    for (int t = 0; t < 8; t++) v[t] = a[SW(base + t * S)];
}
__device__ __forceinline__ void store8(float* a, int base, int S, const float v[8]) {
#pragma unroll
    for (int t = 0; t < 8; t++) a[SW(base + t * S)] = v[t];
}

// Mid radix-8 pass (L = 256 or 32). DIF fwd / DIT inv, same math as before.
__device__ __forceinline__ void pass8_mid(float* re, float* im, const int L,
                                          const float sgn, const bool dit) {
    const int S = L >> 3;
    const int tid = threadIdx.x;
    const int j = tid & (S - 1);
    const int base = ((tid & ~(S - 1)) << 3) + j;
    float xr[8], xi[8];
    load8(re, base, S, xr); load8(im, base, S, xi);
    float ws, wc;
    __sincosf((float)j * (sgn * TWO_PI / (float)L), &ws, &wc);
    if (dit) { twiddle8(xr, xi, wc, ws); dft8(xr, xi, sgn); }
    else     { dft8(xr, xi, sgn); twiddle8(xr, xi, wc, ws); }
    store8(re, base, S, xr); store8(im, base, S, xi);
}

// Fused hub: inverse final pass (L=2048) -> abs*scale -> forward first pass.
__device__ __forceinline__ void hub_abs(float* re, float* im, const float scale) {
    const int t = threadIdx.x;
    float xr[8], xi[8];
    load8(re, t, 256, xr); load8(im, t, 256, xi);
    float ws, wc;
    __sincosf((float)t * (TWO_PI / 2048.0f), &ws, &wc);
    twiddle8(xr, xi, wc, ws);          // inverse DIT input twiddle
    dft8(xr, xi, 1.0f);
#pragma unroll
    for (int s = 0; s < 8; s++) {
        xr[s] = sqrtf(xr[s] * xr[s] + xi[s] * xi[s]) * scale;
        xi[s] = 0.0f;
    }
    dft8(xr, xi, -1.0f);               // forward DIF (imag folds to 0)
    twiddle8(xr, xi, wc, -ws);         // forward output twiddle (conj)
    store8(re, t, 256, xr); store8(im, t, 256, xi);
}

// radix-4 butterfly on a float4 pair
__device__ __forceinline__ void b4(float4& r, float4& q, const float sgn) {
    float t0r = r.x + r.z, t0i = q.x + q.z;
    float t1r = r.x - r.z, t1i = q.x - q.z;
    float t2r = r.y + r.w, t2i = q.y + q.w;
    float t3r = r.y - r.w, t3i = q.y - q.w;
    float it3r = -sgn * t3i, it3i = sgn * t3r;
    r.x = t0r + t2r;  q.x = t0i + t2i;
    r.z = t0r - t2r;  q.z = t0i - t2i;
    r.y = t1r + it3r; q.y = t1i + it3i;
    r.w = t1r - it3r; q.w = t1i - it3i;
}

// Fused hub: forward final pass4 -> (optional global store of spectrum)
// -> multiply by phi -> inverse first pass4.
__device__ __forceinline__ void hub_phi(float* re, float* im,
                                        float* u1r, float* u1i) {
    const int tid = threadIdx.x;
#pragma unroll
    for (int h = 0; h < 2; h++) {
        int c = tid + h * NT;
        int p = SW(c << 2);
        int g = p >> 2;
        float4 r = *(float4*)(re + p);
        float4 q = *(float4*)(im + p);
        b4(r, q, -1.0f);                       // complete forward FFT
        if (u1r) {
            ((float4*)u1r)[g] = r;
            ((float4*)u1i)[g] = q;
        }
        float4 ph = ((const float4*)g_phi)[g];
        r.x *= ph.x; r.y *= ph.y; r.z *= ph.z; r.w *= ph.w;
        q.x *= ph.x; q.y *= ph.y; q.z *= ph.z; q.w *= ph.w;
        b4(r, q, 1.0f);                        // begin inverse FFT
        *(float4*)(re + p) = r;
        *(float4*)(im + p) = q;
    }
}

// Fused prologue: (spectrum * psi) from global -> inverse first pass4 -> smem.
__device__ __forceinline__ void prologue(float* re, float* im,
                                         const float* sr, const float* si,
                                         const float* psi) {
    const int tid = threadIdx.x;
#pragma unroll
    for (int h = 0; h < 2; h++) {
        int c = tid + h * NT;
        int p = SW(c << 2);
        int g = p >> 2;
        float4 ar = ((const float4*)sr)[g];
        float4 ai = ((const float4*)si)[g];
        float4 ps = ((const float4*)psi)[g];
        float4 r, q;
        r.x = ar.x * ps.x; r.y = ar.y * ps.y; r.z = ar.z * ps.z; r.w = ar.w * ps.w;
        q.x = ai.x * ps.x; q.y = ai.y * ps.y; q.z = ai.z * ps.z; q.w = ai.w * ps.w;
        b4(r, q, 1.0f);
        *(float4*)(re + p) = r;
        *(float4*)(im + p) = q;
    }
}

// Fused epilogue: inverse final pass (L=2048) in registers -> mean(log(.)).
__device__ __forceinline__ void epilogue(const float* re, const float* im,
                                         float* red, float* out_elem) {
    const int t = threadIdx.x;
    const float invT = 1.0f / (float)TLEN;
    float xr[8], xi[8];
    load8(re, t, 256, xr); load8(im, t, 256, xi);
    float ws, wc;
    __sincosf((float)t * (TWO_PI / 2048.0f), &ws, &wc);
    twiddle8(xr, xi, wc, ws);
    dft8(xr, xi, 1.0f);
    float s = 0.0f;
#pragma unroll
    for (int k = 0; k < 8; k++) s += __logf(xr[k] * invT + 1e-6f);
    for (int o = 16; o; o >>= 1) s += __shfl_xor_sync(0xFFFFFFFFu, s, o);
    if ((t & 31) == 0) red[t >> 5] = s;
    __syncthreads();
    if (t == 0) {
        float tot = 0.0f;
#pragma unroll
        for (int w = 0; w < NT / 32; w++) tot += red[w];
        *out_elem = tot * invT;
    }
}

// ---------------- filter init (physical slot -> frequency index) ----------------
__global__ void init_filters() {
    int p = blockIdx.x * blockDim.x + threadIdx.x;
    if (p >= TLEN) return;
    int i = SW(p);                          // logical DIF position
    int a = i >> 8, b = (i >> 5) & 7, c = (i >> 2) & 7, d = i & 3;
    int k = a + 8 * b + 64 * c + 512 * d;   // true frequency bin
    float f = (float)(k < 1024 ? k : k - 2048) / 2048.0f;
    const float sigphi = 0.8f * 0.4f * exp2f(-10.0f);
    g_phi[p] = expf(-(f * f) / (2.0f * sigphi * sigphi));
    for (int j = 0; j < N1; j++) {
        float xi  = 0.4f * exp2f(-(float)j / 8.0f);
        float sig = 0.8f * xi / 8.0f;
        float dd  = f - xi;
        g_psi1[j][p] = expf(-dd * dd / (2.0f * sig * sig));
    }
    for (int kk = 0; kk < NK; kk++) {
        float xi  = 0.4f * exp2f(-(float)kk);
        float sig = 0.8f * xi;
        float dd  = f - xi;
        g_psi2[kk][p] = expf(-dd * dd / (2.0f * sig * sig));
    }
}

// ---------------- forward FFT of input signals ----------------
__global__ void __launch_bounds__(NT) fft_x_kernel(const float* __restrict__ x) {
    __shared__ __align__(16) float sre[TLEN], sim[TLEN];
    const int n = blockIdx.x, b = n / NCH, ch = n % NCH;
    const int t = threadIdx.x;
    // fused: global load -> forward first pass (L=2048) -> smem
    {
        float xr[8], xi[8];
#pragma unroll
        for (int s = 0; s < 8; s++) {
            xr[s] = x[(b * TLEN + t + 256 * s) * NCH + ch];
            xi[s] = 0.0f;
        }
        float ws, wc;
        __sincosf((float)t * (-TWO_PI / 2048.0f), &ws, &wc);
        dft8(xr, xi, -1.0f);
        twiddle8(xr, xi, wc, ws);
        store8(sre, t, 256, xr); store8(sim, t, 256, xi);
    }
    __syncthreads();
    pass8_mid(sre, sim, 256, -1.0f, false); __syncthreads();
    pass8_mid(sre, sim, 32,  -1.0f, false); __syncthreads();
    // fused: forward final pass4 -> global store
#pragma unroll
    for (int h = 0; h < 2; h++) {
        int c = t + h * NT;
        int p = SW(c << 2);
        int g = p >> 2;
        float4 r = *(float4*)(sre + p);
        float4 q = *(float4*)(sim + p);
        b4(r, q, -1.0f);
        ((float4*)g_xh_re[n])[g] = r;
        ((float4*)g_xh_im[n])[g] = q;
    }
}

// ---------------- stage 1: one CTA per (signal n, filter j) ----------------
__global__ void __launch_bounds__(NT) stage1_kernel(float* __restrict__ out) {
    __shared__ __align__(16) float sre[TLEN], sim[TLEN];
    __shared__ float red[NT / 32];
    const int n = blockIdx.x, j = blockIdx.y;
    const float invT = 1.0f / (float)TLEN;
    prologue(sre, sim, g_xh_re[n], g_xh_im[n], g_psi1[j]);  __syncthreads();
    pass8_mid(sre, sim, 32,  1.0f, true);  __syncthreads();
    pass8_mid(sre, sim, 256, 1.0f, true);  __syncthreads();
    hub_abs(sre, sim, invT);               __syncthreads();
    pass8_mid(sre, sim, 256, -1.0f, false); __syncthreads();
    pass8_mid(sre, sim, 32,  -1.0f, false); __syncthreads();
    hub_phi(sre, sim, g_u1h_re[n][j], g_u1h_im[n][j]); __syncthreads();
    pass8_mid(sre, sim, 32,  1.0f, true);  __syncthreads();
    pass8_mid(sre, sim, 256, 1.0f, true);  __syncthreads();
    epilogue(sre, sim, red, &out[((n / NCH) * NCOEF + j) * NCH + (n % NCH)]);
}

// ---------------- stage 2: one CTA per (signal n, pair p) ----------------
__global__ void __launch_bounds__(NT) stage2_kernel(float* __restrict__ out) {
    __shared__ __align__(16) float sre[TLEN], sim[TLEN];
    __shared__ float red[NT / 32];
    const int n = blockIdx.x, pid = blockIdx.y;
    const float invT = 1.0f / (float)TLEN;
    int k = 1, pp = pid;
    while (pp >= 8 * k) { pp -= 8 * k; k++; }
    const int j1 = pp;
    prologue(sre, sim, g_u1h_re[n][j1], g_u1h_im[n][j1], g_psi2[k]); __syncthreads();
    pass8_mid(sre, sim, 32,  1.0f, true);  __syncthreads();
    pass8_mid(sre, sim, 256, 1.0f, true);  __syncthreads();
    hub_abs(sre, sim, invT);               __syncthreads();
    pass8_mid(sre, sim, 256, -1.0f, false); __syncthreads();
    pass8_mid(sre, sim, 32,  -1.0f, false); __syncthreads();
    hub_phi(sre, sim, nullptr, nullptr);   __syncthreads();
    pass8_mid(sre, sim, 32,  1.0f, true);  __syncthreads();
    pass8_mid(sre, sim, 256, 1.0f, true);  __syncthreads();
    epilogue(sre, sim, red, &out[((n / NCH) * NCOEF + N1 + pid) * NCH + (n % NCH)]);
}

// ---------------- launcher ----------------
extern "C" void kernel_launch(void* const* d_in, const int* in_sizes, int n_in,
                              void* d_out, int out_size) {
    const float* x = (const float*)d_in[0];   // [8, 2048, 6] f32
    float* out = (float*)d_out;               // [8, 440, 6] f32
    init_filters<<<(TLEN + NT - 1) / NT, NT>>>();
    fft_x_kernel<<<NSAMP, NT>>>(x);
    stage1_kernel<<<dim3(NSAMP, N1), NT>>>(out);
    stage2_kernel<<<dim3(NSAMP, NPAIR), NT>>>(out);
}

// round 4
// speedup vs baseline: 14.0573x; 1.5128x over previous
#include <cuda_runtime.h>
#include <math.h>

// ---------------- problem constants ----------------
#define TLEN   2048
#define NSAMP  48            // B*C = 8*6
#define NCH    6
#define N1     80
#define NK     10
#define NPAIR  360
#define NCOEF  440
#define NT     256
#define SQ2H   0.70710678118654752f
#define TWO_PI 6.28318530717958648f
#define KBINS  5             // phi bins kept: k = 0..4

// ---------------- device scratch (static; no allocations) ----------------
// Frequency-domain arrays stored in SWIZZLED-DIGIT-REVERSED physical order.
__device__ float g_xh_re[NSAMP][TLEN], g_xh_im[NSAMP][TLEN];
__device__ float g_u1h_re[NSAMP][N1][TLEN], g_u1h_im[NSAMP][N1][TLEN];
__device__ float g_psi1[N1][TLEN];
__device__ float g_psi2[NK][TLEN];

// XOR swizzle (involution): conflict-free for pass strides 256/32/4/1.
__device__ __forceinline__ int SW(int i) { return i ^ ((i >> 3) & 28); }

// ---------------- full 8-point DFT (sgn=-1 fwd, +1 inv) ----------------
__device__ __forceinline__ void dft8(float xr[8], float xi[8], const float sgn) {
    float t0r = xr[0] + xr[4], t0i = xi[0] + xi[4];
    float t1r = xr[0] - xr[4], t1i = xi[0] - xi[4];
    float t2r = xr[2] + xr[6], t2i = xi[2] + xi[6];
    float t3r = xr[2] - xr[6], t3i = xi[2] - xi[6];
    float it3r = -sgn * t3i, it3i = sgn * t3r;
    float E0r = t0r + t2r, E0i = t0i + t2i;
    float E2r = t0r - t2r, E2i = t0i - t2i;
    float E1r = t1r + it3r, E1i = t1i + it3i;
    float E3r = t1r - it3r, E3i = t1i - it3i;
    float u0r = xr[1] + xr[5], u0i = xi[1] + xi[5];
    float u1r = xr[1] - xr[5], u1i = xi[1] - xi[5];
    float u2r = xr[3] + xr[7], u2i = xi[3] + xi[7];
    float u3r = xr[3] - xr[7], u3i = xi[3] - xi[7];
    float iu3r = -sgn * u3i, iu3i = sgn * u3r;
    float O0r = u0r + u2r, O0i = u0i + u2i;
    float O2r = u0r - u2r, O2i = u0i - u2i;
    float O1r = u1r + iu3r, O1i = u1i + iu3i;
    float O3r = u1r - iu3r, O3i = u1i - iu3i;
    float w1i = sgn * SQ2H;
    float a1r = O1r * SQ2H - O1i * w1i, a1i = O1r * w1i + O1i * SQ2H;
    float a2r = -sgn * O2i,             a2i = sgn * O2r;
    float a3r = -O3r * SQ2H - O3i * w1i, a3i = O3r * w1i - O3i * SQ2H;
    xr[0] = E0r + O0r; xi[0] = E0i + O0i;
    xr[4] = E0r - O0r; xi[4] = E0i - O0i;
    xr[1] = E1r + a1r; xi[1] = E1i + a1i;
    xr[5] = E1r - a1r; xi[5] = E1i - a1i;
    xr[2] = E2r + a2r; xi[2] = E2i + a2i;
    xr[6] = E2r - a2r; xi[6] = E2i - a2i;
    xr[3] = E3r + a3r; xi[3] = E3i + a3i;
    xr[7] = E3r - a3r; xi[7] = E3i - a3i;
}

// twiddle x[t] *= w^t, w = (c, s), via recurrence
__device__ __forceinline__ void twiddle8(float xr[8], float xi[8],
                                         const float c, const float s) {
    float cr = c, ci = s;
#pragma unroll
    for (int t = 1; t < 8; t++) {
        float r = xr[t] * cr - xi[t] * ci;
        xi[t] = xr[t] * ci + xi[t] * cr; xr[t] = r;
        float nr = cr * c - ci * s; ci = cr * s + ci * c; cr = nr;
    }
}

__device__ __forceinline__ void load8(const float* a, int base, int S, float v[8]) {
#pragma unroll
    for (int t = 0; t < 8; t++) v[t] = a[SW(base + t * S)];
}
__device__ __forceinline__ void store8(float* a, int base, int S, const float v[8]) {
#pragma unroll
    for (int t = 0; t < 8; t++) a[SW(base + t * S)] = v[t];
}

// Mid radix-8 pass (L = 256 or 32). DIF fwd / DIT inv.
__device__ __forceinline__ void pass8_mid(float* re, float* im, const int L,
                                          const float sgn, const bool dit) {
    const int S = L >> 3;
    const int tid = threadIdx.x;
    const int j = tid & (S - 1);
    const int base = ((tid & ~(S - 1)) << 3) + j;
    float xr[8], xi[8];
    load8(re, base, S, xr); load8(im, base, S, xi);
    float ws, wc;
    __sincosf((float)j * (sgn * TWO_PI / (float)L), &ws, &wc);
    if (dit) { twiddle8(xr, xi, wc, ws); dft8(xr, xi, sgn); }
    else     { dft8(xr, xi, sgn); twiddle8(xr, xi, wc, ws); }
    store8(re, base, S, xr); store8(im, base, S, xi);
}

// radix-4 butterfly on a float4 pair
__device__ __forceinline__ void b4(float4& r, float4& q, const float sgn) {
    float t0r = r.x + r.z, t0i = q.x + q.z;
    float t1r = r.x - r.z, t1i = q.x - q.z;
    float t2r = r.y + r.w, t2i = q.y + q.w;
    float t3r = r.y - r.w, t3i = q.y - q.w;
    float it3r = -sgn * t3i, it3i = sgn * t3r;
    r.x = t0r + t2r;  q.x = t0i + t2i;
    r.z = t0r - t2r;  q.z = t0i - t2i;
    r.y = t1r + it3r; q.y = t1i + it3i;
    r.w = t1r - it3r; q.w = t1i - it3i;
}

// Fused prologue: (spectrum * psi) from global -> inverse first pass4 -> smem.
__device__ __forceinline__ void prologue(float* re, float* im,
                                         const float* sr, const float* si,
                                         const float* psi) {
    const int tid = threadIdx.x;
#pragma unroll
    for (int h = 0; h < 2; h++) {
        int c = tid + h * NT;
        int p = SW(c << 2);
        int g = p >> 2;
        float4 ar = ((const float4*)sr)[g];
        float4 ai = ((const float4*)si)[g];
        float4 ps = ((const float4*)psi)[g];
        float4 r, q;
        r.x = ar.x * ps.x; r.y = ar.y * ps.y; r.z = ar.z * ps.z; r.w = ar.w * ps.w;
        q.x = ai.x * ps.x; q.y = ai.y * ps.y; q.z = ai.z * ps.z; q.w = ai.w * ps.w;
        b4(r, q, 1.0f);
        *(float4*)(re + p) = r;
        *(float4*)(im + p) = q;
    }
}

// Fused tail: inverse final pass (L=2048) -> abs*scale -> forward first pass.
// Emits this thread's contribution to bins c_0..c_4 into pr/pi and (optionally)
// stores the forward-first-pass result back to smem to continue the full FFT.
__device__ __forceinline__ void tail_abs(float* re, float* im, const float scale,
                                         float pr[KBINS], float pi[KBINS],
                                         const bool store_back) {
    const int t = threadIdx.x;
    float xr[8], xi[8];
    load8(re, t, 256, xr); load8(im, t, 256, xi);
    float ws, wc;
    __sincosf((float)t * (TWO_PI / 2048.0f), &ws, &wc);
    twiddle8(xr, xi, wc, ws);          // inverse DIT input twiddle
    dft8(xr, xi, 1.0f);                // xr[m] = U[t + 256m] (real)
#pragma unroll
    for (int s = 0; s < 8; s++) {
        xr[s] = sqrtf(xr[s] * xr[s] + xi[s] * xi[s]) * scale;
        xi[s] = 0.0f;
    }
    dft8(xr, xi, -1.0f);               // forward DIF butterfly
    twiddle8(xr, xi, wc, -ws);         // forward output twiddle
#pragma unroll
    for (int k = 0; k < KBINS; k++) { pr[k] = xr[k]; pi[k] = xi[k]; }
    if (store_back) { store8(re, t, 256, xr); store8(im, t, 256, xi); }
}

// Warp-level partial reduce of the 2*KBINS bin partials into smem (no barrier).
__device__ __forceinline__ void bins_warp_reduce(float pr[KBINS], float pi[KBINS],
                                                 float* redc /* [8][2*KBINS] */) {
    const int t = threadIdx.x;
#pragma unroll
    for (int k = 0; k < KBINS; k++) {
        for (int o = 16; o; o >>= 1) {
            pr[k] += __shfl_xor_sync(0xFFFFFFFFu, pr[k], o);
            pi[k] += __shfl_xor_sync(0xFFFFFFFFu, pi[k], o);
        }
    }
    if ((t & 31) == 0) {
        int w = t >> 5;
#pragma unroll
        for (int k = 0; k < KBINS; k++) {
            redc[w * 2 * KBINS + k] = pr[k];
            redc[w * 2 * KBINS + KBINS + k] = pi[k];
        }
    }
}

// Final: sum warp partials -> c_k; reconstruct S via sparse phi; mean(log).
// Requires a __syncthreads() between bins_warp_reduce and this call.
__device__ __forceinline__ void bins_finish(const float* redc, float* redm,
                                            float* out_elem) {
    const int t = threadIdx.x;
    const float invT = 1.0f / (float)TLEN;
    float cr[KBINS], ci[KBINS];
#pragma unroll
    for (int k = 0; k < KBINS; k++) {
        float sr = 0.0f, si = 0.0f;
#pragma unroll
        for (int w = 0; w < 8; w++) {
            sr += redc[w * 2 * KBINS + k];
            si += redc[w * 2 * KBINS + KBINS + k];
        }
        cr[k] = sr; ci[k] = si;
    }
    // phi_k = exp(-1.220703125 * k^2)   (sigma_phi = 0.8*0.4*2^-10)
    const float phk[KBINS] = { 1.0f,
                               expf(-1.220703125f),
                               expf(-4.8828125f),
                               expf(-10.986328125f),
                               expf(-19.53125f) };
    float ws, wc;
    __sincosf((float)t * (TWO_PI / 2048.0f), &ws, &wc);
    // d_k = c_k * phi_k * e^{+2*pi*i*k*t/2048}
    float dr[KBINS], di[KBINS];
    dr[0] = cr[0]; di[0] = ci[0];
    float er = 1.0f, ei = 0.0f;
#pragma unroll
    for (int k = 1; k < KBINS; k++) {
        float nr = er * wc - ei * ws; ei = er * ws + ei * wc; er = nr;
        dr[k] = (cr[k] * er - ci[k] * ei) * phk[k];
        di[k] = (cr[k] * ei + ci[k] * er) * phk[k];
    }
    // 8th roots of unity
    const float C8[8] = {1.f, SQ2H, 0.f, -SQ2H, -1.f, -SQ2H, 0.f, SQ2H};
    const float S8[8] = {0.f, SQ2H, 1.f, SQ2H, 0.f, -SQ2H, -1.f, -SQ2H};
    float s = 0.0f;
#pragma unroll
    for (int m = 0; m < 8; m++) {
        float acc = 0.0f;
#pragma unroll
        for (int k = 1; k < KBINS; k++) {
            int j = (k * m) & 7;
            acc += dr[k] * C8[j] - di[k] * S8[j];
        }
        float Sv = (dr[0] + 2.0f * acc) * invT;
        s += __logf(Sv + 1e-6f);
    }
    for (int o = 16; o; o >>= 1) s += __shfl_xor_sync(0xFFFFFFFFu, s, o);
    if ((t & 31) == 0) redm[t >> 5] = s;
    __syncthreads();
    if (t == 0) {
        float tot = 0.0f;
#pragma unroll
        for (int w = 0; w < 8; w++) tot += redm[w];
        *out_elem = tot * invT;
    }
}

// ---------------- filter init (physical slot -> frequency index) ----------------
__global__ void init_filters() {
    int p = blockIdx.x * blockDim.x + threadIdx.x;
    if (p >= TLEN) return;
    int i = SW(p);                          // logical DIF position
    int a = i >> 8, b = (i >> 5) & 7, c = (i >> 2) & 7, d = i & 3;
    int k = a + 8 * b + 64 * c + 512 * d;   // true frequency bin
    float f = (float)(k < 1024 ? k : k - 2048) / 2048.0f;
    for (int j = 0; j < N1; j++) {
        float xi  = 0.4f * exp2f(-(float)j / 8.0f);
        float sig = 0.8f * xi / 8.0f;
        float dd  = f - xi;
        g_psi1[j][p] = expf(-dd * dd / (2.0f * sig * sig));
    }
    for (int kk = 0; kk < NK; kk++) {
        float xi  = 0.4f * exp2f(-(float)kk);
        float sig = 0.8f * xi;
        float dd  = f - xi;
        g_psi2[kk][p] = expf(-dd * dd / (2.0f * sig * sig));
    }
}

// ---------------- forward FFT of input signals ----------------
__global__ void __launch_bounds__(NT) fft_x_kernel(const float* __restrict__ x) {
    __shared__ __align__(16) float sre[TLEN], sim[TLEN];
    const int n = blockIdx.x, b = n / NCH, ch = n % NCH;
    const int t = threadIdx.x;
    {
        float xr[8], xi[8];
#pragma unroll
        for (int s = 0; s < 8; s++) {
            xr[s] = x[(b * TLEN + t + 256 * s) * NCH + ch];
            xi[s] = 0.0f;
        }
        float ws, wc;
        __sincosf((float)t * (-TWO_PI / 2048.0f), &ws, &wc);
        dft8(xr, xi, -1.0f);
        twiddle8(xr, xi, wc, ws);
        store8(sre, t, 256, xr); store8(sim, t, 256, xi);
    }
    __syncthreads();
    pass8_mid(sre, sim, 256, -1.0f, false); __syncthreads();
    pass8_mid(sre, sim, 32,  -1.0f, false); __syncthreads();
#pragma unroll
    for (int h = 0; h < 2; h++) {
        int c = t + h * NT;
        int p = SW(c << 2);
        int g = p >> 2;
        float4 r = *(float4*)(sre + p);
        float4 q = *(float4*)(sim + p);
        b4(r, q, -1.0f);
        ((float4*)g_xh_re[n])[g] = r;
        ((float4*)g_xh_im[n])[g] = q;
    }
}

// ---------------- stage 1: one CTA per (signal n, filter j) ----------------
__global__ void __launch_bounds__(NT) stage1_kernel(float* __restrict__ out) {
    __shared__ __align__(16) float sre[TLEN], sim[TLEN];
    __shared__ float redc[8 * 2 * KBINS];
    __shared__ float redm[8];
    const int n = blockIdx.x, j = blockIdx.y;
    const int t = threadIdx.x;
    const float invT = 1.0f / (float)TLEN;
    float pr[KBINS], pi[KBINS];
    prologue(sre, sim, g_xh_re[n], g_xh_im[n], g_psi1[j]);  __syncthreads();
    pass8_mid(sre, sim, 32,  1.0f, true);   __syncthreads();
    pass8_mid(sre, sim, 256, 1.0f, true);   __syncthreads();
    tail_abs(sre, sim, invT, pr, pi, true);
    bins_warp_reduce(pr, pi, redc);          __syncthreads();
    pass8_mid(sre, sim, 256, -1.0f, false);  __syncthreads();
    pass8_mid(sre, sim, 32,  -1.0f, false);  __syncthreads();
    // final forward pass4 -> global store of U1h (stage-2 input)
#pragma unroll
    for (int h = 0; h < 2; h++) {
        int c = t + h * NT;
        int p = SW(c << 2);
        int g = p >> 2;
        float4 r = *(float4*)(sre + p);
        float4 q = *(float4*)(sim + p);
        b4(r, q, -1.0f);
        ((float4*)g_u1h_re[n][j])[g] = r;
        ((float4*)g_u1h_im[n][j])[g] = q;
    }
    bins_finish(redc, redm, &out[((n / NCH) * NCOEF + j) * NCH + (n % NCH)]);
}

// ---------------- stage 2: one CTA per (signal n, pair p) ----------------
__global__ void __launch_bounds__(NT) stage2_kernel(float* __restrict__ out) {
    __shared__ __align__(16) float sre[TLEN], sim[TLEN];
    __shared__ float redc[8 * 2 * KBINS];
    __shared__ float redm[8];
    const int n = blockIdx.x, pid = blockIdx.y;
    const float invT = 1.0f / (float)TLEN;
    int k = 1, pp = pid;
    while (pp >= 8 * k) { pp -= 8 * k; k++; }
    const int j1 = pp;
    float pr[KBINS], pi[KBINS];
    prologue(sre, sim, g_u1h_re[n][j1], g_u1h_im[n][j1], g_psi2[k]); __syncthreads();
    pass8_mid(sre, sim, 32,  1.0f, true);  __syncthreads();
    pass8_mid(sre, sim, 256, 1.0f, true);  __syncthreads();
    tail_abs(sre, sim, invT, pr, pi, false);
    bins_warp_reduce(pr, pi, redc);        __syncthreads();
    bins_finish(redc, redm, &out[((n / NCH) * NCOEF + N1 + pid) * NCH + (n % NCH)]);
}

// ---------------- launcher ----------------
extern "C" void kernel_launch(void* const* d_in, const int* in_sizes, int n_in,
                              void* d_out, int out_size) {
    const float* x = (const float*)d_in[0];   // [8, 2048, 6] f32
    float* out = (float*)d_out;               // [8, 440, 6] f32
    init_filters<<<(TLEN + NT - 1) / NT, NT>>>();
    fft_x_kernel<<<NSAMP, NT>>>(x);
    stage1_kernel<<<dim3(NSAMP, N1), NT>>>(out);
    stage2_kernel<<<dim3(NSAMP, NPAIR), NT>>>(out);
}

// round 5
// speedup vs baseline: 17.2269x; 1.2255x over previous
#include <cuda_runtime.h>
#include <math.h>

// ---------------- problem constants ----------------
#define TLEN   2048
#define NSAMP  48            // B*C = 8*6
#define NCH    6
#define N1     80
#define NK     10
#define NPAIR  360
#define NCOEF  440
#define NT     256
#define SQ2H   0.70710678118654752f
#define TWO_PI 6.28318530717958648f
#define KB     4             // phi bins kept: k = 0..3

// ---------------- device scratch (static; no allocations) ----------------
// Frequency-domain arrays stored in SWIZZLED-DIGIT-REVERSED physical order.
__device__ float g_xh_re[NSAMP][TLEN], g_xh_im[NSAMP][TLEN];
__device__ float g_u1h_re[NSAMP][N1][TLEN], g_u1h_im[NSAMP][N1][TLEN];
__device__ float g_psi1[N1][TLEN];
__device__ float g_psi2[NK][TLEN];

// XOR swizzle (involution): conflict-free for pass strides 256/32/4/1.
__device__ __forceinline__ int SW(int i) { return i ^ ((i >> 3) & 28); }

// ---------------- full 8-point DFT (sgn=-1 fwd, +1 inv) ----------------
__device__ __forceinline__ void dft8(float xr[8], float xi[8], const float sgn) {
    float t0r = xr[0] + xr[4], t0i = xi[0] + xi[4];
    float t1r = xr[0] - xr[4], t1i = xi[0] - xi[4];
    float t2r = xr[2] + xr[6], t2i = xi[2] + xi[6];
    float t3r = xr[2] - xr[6], t3i = xi[2] - xi[6];
    float it3r = -sgn * t3i, it3i = sgn * t3r;
    float E0r = t0r + t2r, E0i = t0i + t2i;
    float E2r = t0r - t2r, E2i = t0i - t2i;
    float E1r = t1r + it3r, E1i = t1i + it3i;
    float E3r = t1r - it3r, E3i = t1i - it3i;
    float u0r = xr[1] + xr[5], u0i = xi[1] + xi[5];
    float u1r = xr[1] - xr[5], u1i = xi[1] - xi[5];
    float u2r = xr[3] + xr[7], u2i = xi[3] + xi[7];
    float u3r = xr[3] - xr[7], u3i = xi[3] - xi[7];
    float iu3r = -sgn * u3i, iu3i = sgn * u3r;
    float O0r = u0r + u2r, O0i = u0i + u2i;
    float O2r = u0r - u2r, O2i = u0i - u2i;
    float O1r = u1r + iu3r, O1i = u1i + iu3i;
    float O3r = u1r - iu3r, O3i = u1i - iu3i;
    float w1i = sgn * SQ2H;
    float a1r = O1r * SQ2H - O1i * w1i, a1i = O1r * w1i + O1i * SQ2H;
    float a2r = -sgn * O2i,             a2i = sgn * O2r;
    float a3r = -O3r * SQ2H - O3i * w1i, a3i = O3r * w1i - O3i * SQ2H;
    xr[0] = E0r + O0r; xi[0] = E0i + O0i;
    xr[4] = E0r - O0r; xi[4] = E0i - O0i;
    xr[1] = E1r + a1r; xi[1] = E1i + a1i;
    xr[5] = E1r - a1r; xi[5] = E1i - a1i;
    xr[2] = E2r + a2r; xi[2] = E2i + a2i;
    xr[6] = E2r - a2r; xi[6] = E2i - a2i;
    xr[3] = E3r + a3r; xi[3] = E3i + a3i;
    xr[7] = E3r - a3r; xi[7] = E3i - a3i;
}

// twiddle x[t] *= w^t, w = (c, s), via recurrence
__device__ __forceinline__ void twiddle8(float xr[8], float xi[8],
                                         const float c, const float s) {
    float cr = c, ci = s;
#pragma unroll
    for (int t = 1; t < 8; t++) {
        float r = xr[t] * cr - xi[t] * ci;
        xi[t] = xr[t] * ci + xi[t] * cr; xr[t] = r;
        float nr = cr * c - ci * s; ci = cr * s + ci * c; cr = nr;
    }
}

__device__ __forceinline__ void load8(const float* a, int base, int S, float v[8]) {
#pragma unroll
    for (int t = 0; t < 8; t++) v[t] = a[SW(base + t * S)];
}
__device__ __forceinline__ void store8(float* a, int base, int S, const float v[8]) {
#pragma unroll
    for (int t = 0; t < 8; t++) a[SW(base + t * S)] = v[t];
}

// Mid radix-8 pass (L = 256 or 32). DIF fwd / DIT inv.
__device__ __forceinline__ void pass8_mid(float* re, float* im, const int L,
                                          const float sgn, const bool dit) {
    const int S = L >> 3;
    const int tid = threadIdx.x;
    const int j = tid & (S - 1);
    const int base = ((tid & ~(S - 1)) << 3) + j;
    float xr[8], xi[8];
    load8(re, base, S, xr); load8(im, base, S, xi);
    float ws, wc;
    __sincosf((float)j * (sgn * TWO_PI / (float)L), &ws, &wc);
    if (dit) { twiddle8(xr, xi, wc, ws); dft8(xr, xi, sgn); }
    else     { dft8(xr, xi, sgn); twiddle8(xr, xi, wc, ws); }
    store8(re, base, S, xr); store8(im, base, S, xi);
}

// radix-4 butterfly on a float4 pair
__device__ __forceinline__ void b4(float4& r, float4& q, const float sgn) {
    float t0r = r.x + r.z, t0i = q.x + q.z;
    float t1r = r.x - r.z, t1i = q.x - q.z;
    float t2r = r.y + r.w, t2i = q.y + q.w;
    float t3r = r.y - r.w, t3i = q.y - q.w;
    float it3r = -sgn * t3i, it3i = sgn * t3r;
    r.x = t0r + t2r;  q.x = t0i + t2i;
    r.z = t0r - t2r;  q.z = t0i - t2i;
    r.y = t1r + it3r; q.y = t1i + it3i;
    r.w = t1r - it3r; q.w = t1i - it3i;
}

// Fused prologue: (spectrum * psi) from global -> inverse first pass4 -> smem.
__device__ __forceinline__ void prologue(float* re, float* im,
                                         const float* sr, const float* si,
                                         const float* psi) {
    const int tid = threadIdx.x;
#pragma unroll
    for (int h = 0; h < 2; h++) {
        int c = tid + h * NT;
        int p = SW(c << 2);
        int g = p >> 2;
        float4 ar = ((const float4*)sr)[g];
        float4 ai = ((const float4*)si)[g];
        float4 ps = ((const float4*)psi)[g];
        float4 r, q;
        r.x = ar.x * ps.x; r.y = ar.y * ps.y; r.z = ar.z * ps.z; r.w = ar.w * ps.w;
        q.x = ai.x * ps.x; q.y = ai.y * ps.y; q.z = ai.z * ps.z; q.w = ai.w * ps.w;
        b4(r, q, 1.0f);
        *(float4*)(re + p) = r;
        *(float4*)(im + p) = q;
    }
}

// ---- stage-2 tail: inverse final pass -> abs -> REDUCED real-input fwd DFT ----
// Produces only bins 0..3 (pr/pi) and the per-thread twiddle (wc, ws).
__device__ __forceinline__ void tail_lite(const float* re, const float* im,
                                          const float scale,
                                          float pr[KB], float pi[KB],
                                          float& owc, float& ows) {
    const int t = threadIdx.x;
    float xr[8], xi[8];
    load8(re, t, 256, xr); load8(im, t, 256, xi);
    float ws, wc;
    __sincosf((float)t * (TWO_PI / 2048.0f), &ws, &wc);
    owc = wc; ows = ws;
    twiddle8(xr, xi, wc, ws);          // inverse DIT input twiddle
    dft8(xr, xi, 1.0f);                // xr[m] = U[t + 256m]
    float U[8];
#pragma unroll
    for (int s = 0; s < 8; s++)
        U[s] = sqrtf(xr[s] * xr[s] + xi[s] * xi[s]) * scale;
    // real-input 8-point DFT, outputs k=0..3 only
    float a0 = U[0] + U[4], a1 = U[1] + U[5], a2 = U[2] + U[6], a3 = U[3] + U[7];
    float d0 = U[0] - U[4], d1 = U[1] - U[5], d2 = U[2] - U[6], d3 = U[3] - U[7];
    float s13 = SQ2H * (d1 + d3), m13 = SQ2H * (d1 - d3);
    float y0r = (a0 + a2) + (a1 + a3);
    float y1r = d0 + m13,  y1i = -d2 - s13;
    float y2r = a0 - a2,   y2i = a3 - a1;
    float y3r = d0 - m13,  y3i = d2 - s13;
    // forward output twiddle w^k with w = (wc, -ws)
    float w2r = wc * wc - ws * ws, w2i = -2.0f * wc * ws;
    float w3r = w2r * wc + w2i * ws, w3i = -w2r * ws + w2i * wc;
    pr[0] = y0r;                          pi[0] = 0.0f;
    pr[1] = y1r * wc + y1i * ws;          pi[1] = -y1r * ws + y1i * wc;
    pr[2] = y2r * w2r - y2i * w2i;        pi[2] = y2r * w2i + y2i * w2r;
    pr[3] = y3r * w3r - y3i * w3i;        pi[3] = y3r * w3i + y3i * w3r;
}

// ---- stage-1 tail: same but full forward first pass kept + stored back ----
__device__ __forceinline__ void tail_full(float* re, float* im, const float scale,
                                          float pr[KB], float pi[KB],
                                          float& owc, float& ows) {
    const int t = threadIdx.x;
    float xr[8], xi[8];
    load8(re, t, 256, xr); load8(im, t, 256, xi);
    float ws, wc;
    __sincosf((float)t * (TWO_PI / 2048.0f), &ws, &wc);
    owc = wc; ows = ws;
    twiddle8(xr, xi, wc, ws);
    dft8(xr, xi, 1.0f);
#pragma unroll
    for (int s = 0; s < 8; s++) {
        xr[s] = sqrtf(xr[s] * xr[s] + xi[s] * xi[s]) * scale;
        xi[s] = 0.0f;
    }
    dft8(xr, xi, -1.0f);               // forward DIF (imag inputs fold to 0)
    twiddle8(xr, xi, wc, -ws);
#pragma unroll
    for (int k = 0; k < KB; k++) { pr[k] = xr[k]; pi[k] = xi[k]; }
    store8(re, t, 256, xr); store8(im, t, 256, xi);
}

// ---- bins reduction: smem transpose-reduce (scratch = sre, 2048 floats) ----
__device__ __forceinline__ void bins_store(const float pr[KB], const float pi[KB],
                                           float* scratch) {
    const int t = threadIdx.x;
#pragma unroll
    for (int k = 0; k < KB; k++) {
        scratch[k * NT + t]        = pr[k];
        scratch[(k + KB) * NT + t] = pi[k];
    }
}
__device__ __forceinline__ void bins_sum(const float* scratch, float* cb) {
    const int w = threadIdx.x >> 5, l = threadIdx.x & 31;
    float s = 0.0f;
#pragma unroll
    for (int m = 0; m < 8; m++) s += scratch[w * NT + l + 32 * m];
#pragma unroll
    for (int o = 16; o; o >>= 1) s += __shfl_xor_sync(0xFFFFFFFFu, s, o);
    if (l == 0) cb[w] = s;
}

// ---- final: reconstruct S from 4 bins, mean(log). needs sync before. ----
__device__ __forceinline__ void bins_finish(const float* cb, const float wc,
                                            const float ws, float* redm,
                                            float* out_elem) {
    const int t = threadIdx.x;
    const float invT = 1.0f / (float)TLEN;
    // phi_k = exp(-1.220703125 * k^2)
    const float ph1 = 0.29502258f, ph2 = 0.0075757135f, ph3 = 1.6931630e-5f;
    float c1r = cb[1], c2r = cb[2], c3r = cb[3];
    float c1i = cb[5], c2i = cb[6], c3i = cb[7];
    float d0 = cb[0];
    // e^{+i*2*pi*k*t/2048} from (wc, ws)
    float e2r = wc * wc - ws * ws, e2i = 2.0f * wc * ws;
    float e3r = e2r * wc - e2i * ws, e3i = e2r * ws + e2i * wc;
    float d1r = (c1r * wc - c1i * ws) * ph1, d1i = (c1r * ws + c1i * wc) * ph1;
    float d2r = (c2r * e2r - c2i * e2i) * ph2, d2i = (c2r * e2i + c2i * e2r) * ph2;
    float d3r = (c3r * e3r - c3i * e3i) * ph3, d3i = (c3r * e3i + c3i * e3r) * ph3;
    const float C8[8] = {1.f, SQ2H, 0.f, -SQ2H, -1.f, -SQ2H, 0.f, SQ2H};
    const float S8[8] = {0.f, SQ2H, 1.f, SQ2H, 0.f, -SQ2H, -1.f, -SQ2H};
    float s = 0.0f;
#pragma unroll
    for (int m = 0; m < 8; m++) {
        float acc = d1r * C8[m] - d1i * S8[m]
                  + d2r * C8[(2 * m) & 7] - d2i * S8[(2 * m) & 7]
                  + d3r * C8[(3 * m) & 7] - d3i * S8[(3 * m) & 7];
        s += __logf((d0 + 2.0f * acc) * invT + 1e-6f);
    }
#pragma unroll
    for (int o = 16; o; o >>= 1) s += __shfl_xor_sync(0xFFFFFFFFu, s, o);
    if ((t & 31) == 0) redm[t >> 5] = s;
    __syncthreads();
    if (t == 0) {
        float tot = 0.0f;
#pragma unroll
        for (int w = 0; w < 8; w++) tot += redm[w];
        *out_elem = tot * invT;
    }
}

// ---------------- filter init (physical slot -> frequency index) ----------------
__global__ void init_filters() {
    int p = blockIdx.x * blockDim.x + threadIdx.x;
    if (p >= TLEN) return;
    int i = SW(p);                          // logical DIF position
    int a = i >> 8, b = (i >> 5) & 7, c = (i >> 2) & 7, d = i & 3;
    int k = a + 8 * b + 64 * c + 512 * d;   // true frequency bin
    float f = (float)(k < 1024 ? k : k - 2048) / 2048.0f;
    for (int j = 0; j < N1; j++) {
        float xi  = 0.4f * exp2f(-(float)j / 8.0f);
        float sig = 0.8f * xi / 8.0f;
        float dd  = f - xi;
        g_psi1[j][p] = expf(-dd * dd / (2.0f * sig * sig));
    }
    for (int kk = 0; kk < NK; kk++) {
        float xi  = 0.4f * exp2f(-(float)kk);
        float sig = 0.8f * xi;
        float dd  = f - xi;
        g_psi2[kk][p] = expf(-dd * dd / (2.0f * sig * sig));
    }
}

// ---------------- forward FFT of input signals ----------------
__global__ void __launch_bounds__(NT) fft_x_kernel(const float* __restrict__ x) {
    __shared__ __align__(16) float sre[TLEN], sim[TLEN];
    const int n = blockIdx.x, b = n / NCH, ch = n % NCH;
    const int t = threadIdx.x;
    {
        float xr[8], xi[8];
#pragma unroll
        for (int s = 0; s < 8; s++) {
            xr[s] = x[(b * TLEN + t + 256 * s) * NCH + ch];
            xi[s] = 0.0f;
        }
        float ws, wc;
        __sincosf((float)t * (-TWO_PI / 2048.0f), &ws, &wc);
        dft8(xr, xi, -1.0f);
        twiddle8(xr, xi, wc, ws);
        store8(sre, t, 256, xr); store8(sim, t, 256, xi);
    }
    __syncthreads();
    pass8_mid(sre, sim, 256, -1.0f, false); __syncthreads();
    pass8_mid(sre, sim, 32,  -1.0f, false); __syncthreads();
#pragma unroll
    for (int h = 0; h < 2; h++) {
        int c = t + h * NT;
        int p = SW(c << 2);
        int g = p >> 2;
        float4 r = *(float4*)(sre + p);
        float4 q = *(float4*)(sim + p);
        b4(r, q, -1.0f);
        ((float4*)g_xh_re[n])[g] = r;
        ((float4*)g_xh_im[n])[g] = q;
    }
}

// ---------------- stage 1: one CTA per (signal n, filter j) ----------------
__global__ void __launch_bounds__(NT) stage1_kernel(float* __restrict__ out) {
    __shared__ __align__(16) float sre[TLEN], sim[TLEN];
    __shared__ float cb[2 * KB];
    __shared__ float redm[8];
    const int n = blockIdx.x, j = blockIdx.y;
    const int t = threadIdx.x;
    const float invT = 1.0f / (float)TLEN;
    float pr[KB], pi[KB], wc, ws;
    prologue(sre, sim, g_xh_re[n], g_xh_im[n], g_psi1[j]);  __syncthreads();
    pass8_mid(sre, sim, 32,  1.0f, true);   __syncthreads();
    pass8_mid(sre, sim, 256, 1.0f, true);   __syncthreads();
    tail_full(sre, sim, invT, pr, pi, wc, ws); __syncthreads();
    pass8_mid(sre, sim, 256, -1.0f, false);  __syncthreads();
    pass8_mid(sre, sim, 32,  -1.0f, false);  __syncthreads();
    // final forward pass4 -> global store of U1h (stage-2 input)
#pragma unroll
    for (int h = 0; h < 2; h++) {
        int c = t + h * NT;
        int p = SW(c << 2);
        int g = p >> 2;
        float4 r = *(float4*)(sre + p);
        float4 q = *(float4*)(sim + p);
        b4(r, q, -1.0f);
        ((float4*)g_u1h_re[n][j])[g] = r;
        ((float4*)g_u1h_im[n][j])[g] = q;
    }
    __syncthreads();                 // all reads of sre done; reuse as scratch
    bins_store(pr, pi, sre);         __syncthreads();
    bins_sum(sre, cb);               __syncthreads();
    bins_finish(cb, wc, ws, redm,
                &out[((n / NCH) * NCOEF + j) * NCH + (n % NCH)]);
}

// ---------------- stage 2: one CTA per (signal n, pair p) ----------------
__global__ void __launch_bounds__(NT) stage2_kernel(float* __restrict__ out) {
    __shared__ __align__(16) float sre[TLEN], sim[TLEN];
    __shared__ float cb[2 * KB];
    __shared__ float redm[8];
    const int n = blockIdx.x, pid = blockIdx.y;
    const float invT = 1.0f / (float)TLEN;
    int k = 1, pp = pid;
    while (pp >= 8 * k) { pp -= 8 * k; k++; }
    const int j1 = pp;
    float pr[KB], pi[KB], wc, ws;
    prologue(sre, sim, g_u1h_re[n][j1], g_u1h_im[n][j1], g_psi2[k]); __syncthreads();
    pass8_mid(sre, sim, 32,  1.0f, true);  __syncthreads();
    pass8_mid(sre, sim, 256, 1.0f, true);  __syncthreads();
    tail_lite(sre, sim, invT, pr, pi, wc, ws);
    __syncthreads();                 // all reads of sre done; reuse as scratch
    bins_store(pr, pi, sre);         __syncthreads();
    bins_sum(sre, cb);               __syncthreads();
    bins_finish(cb, wc, ws, redm,
                &out[((n / NCH) * NCOEF + N1 + pid) * NCH + (n % NCH)]);
}

// ---------------- launcher ----------------
extern "C" void kernel_launch(void* const* d_in, const int* in_sizes, int n_in,
                              void* d_out, int out_size) {
    const float* x = (const float*)d_in[0];   // [8, 2048, 6] f32
    float* out = (float*)d_out;               // [8, 440, 6] f32
    init_filters<<<(TLEN + NT - 1) / NT, NT>>>();
    fft_x_kernel<<<NSAMP, NT>>>(x);
    stage1_kernel<<<dim3(NSAMP, N1), NT>>>(out);
    stage2_kernel<<<dim3(NSAMP, NPAIR), NT>>>(out);
}